// round 17
// baseline (speedup 1.0000x reference)
#include <cuda_runtime.h>

// Problem constants
#define Bn 8
#define Tn 2048
#define Cn 1024
#define Hn 64
#define Mn (Bn * Tn)   // 16384 rows

// Scratch (device globals: no runtime allocation)
__device__ float g_Q[(size_t)Mn * Hn];
__device__ float g_K[(size_t)Mn * Hn];
__device__ float g_V[(size_t)Mn * Hn];
// split-K partials: [b][qt][split][64 rows][64 cols] and per-row stats
__device__ float g_pO[(size_t)8 * 32 * 4 * 64 * 64];
__device__ float g_pm[(size_t)8 * 32 * 4 * 64];
__device__ float g_pl[(size_t)8 * 32 * 4 * 64];

// ---------------------------------------------------------------------------
// Helpers
// ---------------------------------------------------------------------------
__device__ __forceinline__ float f2tf(float f) {
    unsigned u;
    asm("cvt.rna.tf32.f32 %0, %1;" : "=r"(u) : "f"(f));
    return __uint_as_float(u);
}

__device__ __forceinline__ void mma_tf32(float& d0, float& d1, float& d2, float& d3,
                                         unsigned a0, unsigned a1, unsigned a2, unsigned a3,
                                         unsigned b0, unsigned b1)
{
    asm volatile(
        "mma.sync.aligned.m16n8k8.row.col.f32.tf32.tf32.f32 "
        "{%0,%1,%2,%3}, {%4,%5,%6,%7}, {%8,%9}, {%0,%1,%2,%3};\n"
        : "+f"(d0), "+f"(d1), "+f"(d2), "+f"(d3)
        : "r"(a0), "r"(a1), "r"(a2), "r"(a3), "r"(b0), "r"(b1));
}

// k16-chunk swizzled smem index (bank-conflict-free LDS.128 fragment loads)
__device__ __forceinline__ int swz(int row, int c4, int k4) {
    return row * 16 + (((c4 ^ (row & 3))) << 2) + k4;
}

// ---------------------------------------------------------------------------
// Kernel 1: fused QKV projection via tf32 mma.
// BM=32, BN=192, BK=16, 256 threads = 8 warps as 2(m) x 4(n), warp tile 16x48.
// Grid = 512 CTAs. Low register pressure (~75) -> 3 CTAs/SM.
// ---------------------------------------------------------------------------
__global__ __launch_bounds__(256)
void qkv_mma(const float* __restrict__ x, const float* __restrict__ Wq,
             const float* __restrict__ Wk, const float* __restrict__ Wv)
{
    __shared__ __align__(16) float As[2][32 * 16];
    __shared__ __align__(16) float Bs[2][192 * 16];

    const int t    = threadIdx.x;
    const int lane = t & 31;
    const int warp = t >> 5;
    const int g    = lane >> 2;
    const int q4   = lane & 3;
    const int wm   = warp >> 2;   // 0..1
    const int wn   = warp & 3;    // 0..3
    const int m0   = blockIdx.x * 32;

    // A gmem: threads 0..127 -> (row = t/4, k-quad = t%4)
    const int arow = t >> 2;
    const int au   = t & 3;
    const float* aptr = x + (size_t)(m0 + (arow & 31)) * Cn + au * 4;
    const bool aact = (t < 128);

    // B gmem: 768 float4 per tile, 3 per thread
    int bk[3], bn[3];
    const float* bp[3];
#pragma unroll
    for (int r = 0; r < 3; ++r) {
        int f  = t + 256 * r;
        int k  = f / 48;
        int n  = (f % 48) * 4;
        bk[r] = k; bn[r] = n;
        const float* W = (n < 64) ? Wq : (n < 128) ? Wk : Wv;
        bp[r] = W + (size_t)k * Hn + (n & 63);
    }

    float acc[6][4];
#pragma unroll
    for (int j = 0; j < 6; ++j)
#pragma unroll
        for (int e = 0; e < 4; ++e) acc[j][e] = 0.f;

    float4 aR = make_float4(0.f, 0.f, 0.f, 0.f), bR[3];

    // prologue
    if (aact) aR = *(const float4*)aptr;
#pragma unroll
    for (int r = 0; r < 3; ++r) bR[r] = *(const float4*)(bp[r]);
    {
        if (aact) {
            float av[4] = {aR.x, aR.y, aR.z, aR.w};
#pragma unroll
            for (int e = 0; e < 4; ++e) As[0][swz(arow, e, au)] = f2tf(av[e]);
        }
#pragma unroll
        for (int r = 0; r < 3; ++r) {
            float bv[4] = {bR[r].x, bR[r].y, bR[r].z, bR[r].w};
#pragma unroll
            for (int e = 0; e < 4; ++e)
                Bs[0][swz(bn[r] + e, bk[r] & 3, bk[r] >> 2)] = f2tf(bv[e]);
        }
    }
    __syncthreads();

    const int rA = wm * 16 + g;
    const int rB = rA + 8;

    for (int it = 0; it < Cn / 16; ++it) {
        const int s = it & 1;
        if (it < Cn / 16 - 1) {
            if (aact) aR = *(const float4*)(aptr + (it + 1) * 16);
#pragma unroll
            for (int r = 0; r < 3; ++r)
                bR[r] = *(const float4*)(bp[r] + (size_t)(it + 1) * 16 * Hn);
        }

        // A fragments (two k8 steps)
        float4 lo = *(const float4*)&As[s][swz(rA, q4, 0)];
        float4 hi = *(const float4*)&As[s][swz(rB, q4, 0)];
        unsigned a0[4] = {__float_as_uint(lo.x), __float_as_uint(hi.x),
                          __float_as_uint(lo.y), __float_as_uint(hi.y)};
        unsigned a1[4] = {__float_as_uint(lo.z), __float_as_uint(hi.z),
                          __float_as_uint(lo.w), __float_as_uint(hi.w)};

#pragma unroll
        for (int j = 0; j < 6; ++j) {
            int n = wn * 48 + 8 * j + g;
            float4 bv = *(const float4*)&Bs[s][swz(n, q4, 0)];
            mma_tf32(acc[j][0], acc[j][1], acc[j][2], acc[j][3],
                     a0[0], a0[1], a0[2], a0[3],
                     __float_as_uint(bv.x), __float_as_uint(bv.y));
            mma_tf32(acc[j][0], acc[j][1], acc[j][2], acc[j][3],
                     a1[0], a1[1], a1[2], a1[3],
                     __float_as_uint(bv.z), __float_as_uint(bv.w));
        }

        if (it < Cn / 16 - 1) {
            const int d = s ^ 1;
            if (aact) {
                float av[4] = {aR.x, aR.y, aR.z, aR.w};
#pragma unroll
                for (int e = 0; e < 4; ++e) As[d][swz(arow, e, au)] = f2tf(av[e]);
            }
#pragma unroll
            for (int r = 0; r < 3; ++r) {
                float bv[4] = {bR[r].x, bR[r].y, bR[r].z, bR[r].w};
#pragma unroll
                for (int e = 0; e < 4; ++e)
                    Bs[d][swz(bn[r] + e, bk[r] & 3, bk[r] >> 2)] = f2tf(bv[e]);
            }
        }
        __syncthreads();
    }

    // epilogue
    {
        int row = m0 + rA;
#pragma unroll
        for (int j = 0; j < 6; ++j) {
            int nn = wn * 48 + 8 * j;
            float* dst = (nn < 64) ? g_Q : (nn < 128) ? g_K : g_V;
            float sc = (nn < 64) ? 0.125f : 1.0f;
            int col = (nn & 63) + 2 * q4;
            *(float2*)&dst[(size_t)row * Hn + col] =
                make_float2(acc[j][0] * sc, acc[j][1] * sc);
            *(float2*)&dst[(size_t)(row + 8) * Hn + col] =
                make_float2(acc[j][2] * sc, acc[j][3] * sc);
        }
    }
}

// ---------------------------------------------------------------------------
// Kernel 2: split-K causal flash attention via tf32 mma.
// CTA = (b, 64-query tile qt, split sp). Split sp handles key-tiles
// [sp*8, min(sp*8+8, qt+1)). 640 CTAs total (vs 256), near-uniform work.
// 128 threads = 4 warps x 16 query rows. Partials to scratch unless NS==1.
// ---------------------------------------------------------------------------
__global__ __launch_bounds__(128, 3)
void attn_mma(float* __restrict__ out)
{
    __shared__ __align__(16) float Ps[64 * 64];  // Q (chunked), then P
    __shared__ __align__(16) float Ks[64 * 64];
    __shared__ __align__(16) float Vs[64 * 64];

    const int t    = threadIdx.x;
    const int lane = t & 31;
    const int warp = t >> 5;
    const int g    = lane >> 2;
    const int q4   = lane & 3;
    const int b    = blockIdx.y;

    // decode blockIdx.x (0..79) -> (qt descending = heavy first, split sp)
    int wid = blockIdx.x;
    int qt = 31;
    for (;;) {
        int ns = (qt >> 3) + 1;
        if (wid < ns) break;
        wid -= ns; --qt;
    }
    const int sp  = wid;
    const int NS  = (qt >> 3) + 1;
    const int jt0 = sp * 8;
    const int jt1 = min(jt0 + 8, qt + 1);
    const int q0  = qt * 64;

    // ---- load Q (tf32) into chunked smem ----
    {
        const float* Qg = g_Q + ((size_t)b * Tn + q0) * Hn;
        for (int i4 = t; i4 < 1024; i4 += 128) {
            int row = i4 >> 4, u4 = i4 & 15;
            float4 v = *(const float4*)&Qg[row * Hn + u4 * 4];
            int kc = u4 >> 2, k4 = u4 & 3;
            float* base = &Ps[kc * 1024];
            float av[4] = {v.x, v.y, v.z, v.w};
#pragma unroll
            for (int e = 0; e < 4; ++e) base[swz(row, e, k4)] = f2tf(av[e]);
        }
    }
    __syncthreads();

    const int rA = warp * 16 + g;
    const int rB = rA + 8;

    unsigned qA[8][4];
#pragma unroll
    for (int kc = 0; kc < 4; ++kc) {
        float4 lo = *(const float4*)&Ps[kc * 1024 + swz(rA, q4, 0)];
        float4 hi = *(const float4*)&Ps[kc * 1024 + swz(rB, q4, 0)];
        qA[2*kc][0]   = __float_as_uint(lo.x); qA[2*kc][1]   = __float_as_uint(hi.x);
        qA[2*kc][2]   = __float_as_uint(lo.y); qA[2*kc][3]   = __float_as_uint(hi.y);
        qA[2*kc+1][0] = __float_as_uint(lo.z); qA[2*kc+1][1] = __float_as_uint(hi.z);
        qA[2*kc+1][2] = __float_as_uint(lo.w); qA[2*kc+1][3] = __float_as_uint(hi.w);
    }

    float O[8][4];
#pragma unroll
    for (int j = 0; j < 8; ++j)
#pragma unroll
        for (int e = 0; e < 4; ++e) O[j][e] = 0.f;
    float mA = -1e30f, mB = -1e30f, lA = 0.f, lB = 0.f;

    for (int jt = jt0; jt < jt1; ++jt) {
        __syncthreads();

        // ---- load K (direct) + V (transposed) ----
        {
            const float* Kg = g_K + ((size_t)b * Tn + jt * 64) * Hn;
            const float* Vg = g_V + ((size_t)b * Tn + jt * 64) * Hn;
            for (int i4 = t; i4 < 1024; i4 += 128) {
                int row = i4 >> 4, u4 = i4 & 15;
                float4 v = *(const float4*)&Kg[row * Hn + u4 * 4];
                int kc = u4 >> 2, k4 = u4 & 3;
                float* base = &Ks[kc * 1024];
                float av[4] = {v.x, v.y, v.z, v.w};
#pragma unroll
                for (int e = 0; e < 4; ++e) base[swz(row, e, k4)] = f2tf(av[e]);
            }
            for (int i4 = t; i4 < 1024; i4 += 128) {
                int key = i4 >> 4, u4 = i4 & 15;
                float4 v = *(const float4*)&Vg[key * Hn + u4 * 4];
                int kc = key >> 4, c4 = key & 3, k4 = (key >> 2) & 3;
                float* base = &Vs[kc * 1024];
                float av[4] = {v.x, v.y, v.z, v.w};
#pragma unroll
                for (int e = 0; e < 4; ++e) {
                    int d = u4 * 4 + e;
                    base[swz(d, c4, k4)] = f2tf(av[e]);
                }
            }
        }
        __syncthreads();

        // ---- S = Q @ K^T ----
        float S[8][4];
#pragma unroll
        for (int j = 0; j < 8; ++j)
#pragma unroll
            for (int e = 0; e < 4; ++e) S[j][e] = 0.f;

#pragma unroll
        for (int kc = 0; kc < 4; ++kc) {
#pragma unroll
            for (int jb = 0; jb < 8; jb += 4) {
                float4 kf[4];
#pragma unroll
                for (int j = 0; j < 4; ++j) {
                    int n = 8 * (jb + j) + g;
                    kf[j] = *(const float4*)&Ks[kc * 1024 + swz(n, q4, 0)];
                }
#pragma unroll
                for (int j = 0; j < 4; ++j) {
                    int jj = jb + j;
                    mma_tf32(S[jj][0], S[jj][1], S[jj][2], S[jj][3],
                             qA[2*kc][0], qA[2*kc][1], qA[2*kc][2], qA[2*kc][3],
                             __float_as_uint(kf[j].x), __float_as_uint(kf[j].y));
                    mma_tf32(S[jj][0], S[jj][1], S[jj][2], S[jj][3],
                             qA[2*kc+1][0], qA[2*kc+1][1], qA[2*kc+1][2], qA[2*kc+1][3],
                             __float_as_uint(kf[j].z), __float_as_uint(kf[j].w));
                }
            }
        }

        // ---- causal mask (diagonal tile only) ----
        if (jt == qt) {
#pragma unroll
            for (int j = 0; j < 8; ++j) {
                int c = 8 * j + 2 * q4;
                if (c     > rA) S[j][0] = -1e30f;
                if (c + 1 > rA) S[j][1] = -1e30f;
                if (c     > rB) S[j][2] = -1e30f;
                if (c + 1 > rB) S[j][3] = -1e30f;
            }
        }

        // ---- online softmax ----
        float mxA = -1e30f, mxB = -1e30f;
#pragma unroll
        for (int j = 0; j < 8; ++j) {
            mxA = fmaxf(mxA, fmaxf(S[j][0], S[j][1]));
            mxB = fmaxf(mxB, fmaxf(S[j][2], S[j][3]));
        }
        mxA = fmaxf(mxA, __shfl_xor_sync(0xffffffffu, mxA, 1));
        mxA = fmaxf(mxA, __shfl_xor_sync(0xffffffffu, mxA, 2));
        mxB = fmaxf(mxB, __shfl_xor_sync(0xffffffffu, mxB, 1));
        mxB = fmaxf(mxB, __shfl_xor_sync(0xffffffffu, mxB, 2));

        float nmA = fmaxf(mA, mxA), nmB = fmaxf(mB, mxB);
        float fA = __expf(mA - nmA), fB = __expf(mB - nmB);
        mA = nmA; mB = nmB;

        float sA = 0.f, sB = 0.f;
#pragma unroll
        for (int j = 0; j < 8; ++j) {
            S[j][0] = __expf(S[j][0] - nmA); sA += S[j][0];
            S[j][1] = __expf(S[j][1] - nmA); sA += S[j][1];
            S[j][2] = __expf(S[j][2] - nmB); sB += S[j][2];
            S[j][3] = __expf(S[j][3] - nmB); sB += S[j][3];
        }
        lA = lA * fA + sA;
        lB = lB * fB + sB;
#pragma unroll
        for (int j = 0; j < 8; ++j) {
            O[j][0] *= fA; O[j][1] *= fA;
            O[j][2] *= fB; O[j][3] *= fB;
        }

        // ---- store P into freed Q buffer (warp-local rows) ----
#pragma unroll
        for (int j = 0; j < 8; ++j) {
            int c0 = 8 * j + 2 * q4, c1 = c0 + 1;
            Ps[(c0 >> 4) * 1024 + rA * 16 + (((c0 & 3) ^ (rA & 3)) << 2) + ((c0 >> 2) & 3)] = f2tf(S[j][0]);
            Ps[(c1 >> 4) * 1024 + rA * 16 + (((c1 & 3) ^ (rA & 3)) << 2) + ((c1 >> 2) & 3)] = f2tf(S[j][1]);
            Ps[(c0 >> 4) * 1024 + rB * 16 + (((c0 & 3) ^ (rB & 3)) << 2) + ((c0 >> 2) & 3)] = f2tf(S[j][2]);
            Ps[(c1 >> 4) * 1024 + rB * 16 + (((c1 & 3) ^ (rB & 3)) << 2) + ((c1 >> 2) & 3)] = f2tf(S[j][3]);
        }
        __syncwarp();

        // ---- O += P @ V ----
#pragma unroll
        for (int kc = 0; kc < 4; ++kc) {
            float4 pLo = *(const float4*)&Ps[kc * 1024 + swz(rA, q4, 0)];
            float4 pHi = *(const float4*)&Ps[kc * 1024 + swz(rB, q4, 0)];
            unsigned a00 = __float_as_uint(pLo.x), a01 = __float_as_uint(pHi.x);
            unsigned a02 = __float_as_uint(pLo.y), a03 = __float_as_uint(pHi.y);
            unsigned a10 = __float_as_uint(pLo.z), a11 = __float_as_uint(pHi.z);
            unsigned a12 = __float_as_uint(pLo.w), a13 = __float_as_uint(pHi.w);
#pragma unroll
            for (int jb = 0; jb < 8; jb += 4) {
                float4 vf[4];
#pragma unroll
                for (int j = 0; j < 4; ++j) {
                    int n = 8 * (jb + j) + g;
                    vf[j] = *(const float4*)&Vs[kc * 1024 + swz(n, q4, 0)];
                }
#pragma unroll
                for (int j = 0; j < 4; ++j) {
                    int jj = jb + j;
                    mma_tf32(O[jj][0], O[jj][1], O[jj][2], O[jj][3],
                             a00, a01, a02, a03,
                             __float_as_uint(vf[j].x), __float_as_uint(vf[j].y));
                    mma_tf32(O[jj][0], O[jj][1], O[jj][2], O[jj][3],
                             a10, a11, a12, a13,
                             __float_as_uint(vf[j].z), __float_as_uint(vf[j].w));
                }
            }
        }
    }

    // ---- finalize: reduce l across quad ----
    lA += __shfl_xor_sync(0xffffffffu, lA, 1);
    lA += __shfl_xor_sync(0xffffffffu, lA, 2);
    lB += __shfl_xor_sync(0xffffffffu, lB, 1);
    lB += __shfl_xor_sync(0xffffffffu, lB, 2);

    if (NS == 1) {
        float invA = 1.f / lA, invB = 1.f / lB;
        size_t rowAg = (size_t)b * Tn + q0 + rA;
        size_t rowBg = rowAg + 8;
#pragma unroll
        for (int j = 0; j < 8; ++j) {
            int c = 8 * j + 2 * q4;
            *(float2*)&out[rowAg * Hn + c] = make_float2(O[j][0] * invA, O[j][1] * invA);
            *(float2*)&out[rowBg * Hn + c] = make_float2(O[j][2] * invB, O[j][3] * invB);
        }
    } else {
        size_t pbase = ((size_t)(b * 32 + qt) * 4 + sp) * 4096;
#pragma unroll
        for (int j = 0; j < 8; ++j) {
            int c = 8 * j + 2 * q4;
            *(float2*)&g_pO[pbase + rA * 64 + c] = make_float2(O[j][0], O[j][1]);
            *(float2*)&g_pO[pbase + rB * 64 + c] = make_float2(O[j][2], O[j][3]);
        }
        if (q4 == 0) {
            size_t st = ((size_t)(b * 32 + qt) * 4 + sp) * 64;
            g_pm[st + rA] = mA; g_pl[st + rA] = lA;
            g_pm[st + rB] = mB; g_pl[st + rB] = lB;
        }
    }
}

// ---------------------------------------------------------------------------
// Kernel 3: merge split-K partials for qt >= 8.
// ---------------------------------------------------------------------------
__global__ __launch_bounds__(256)
void attn_merge(float* __restrict__ out)
{
    const int qt = 8 + blockIdx.x;     // 8..31
    const int b  = blockIdx.y;
    const int NS = (qt >> 3) + 1;      // 2..4
    const int t  = threadIdx.x;
    const int row = t >> 2;
    const int cb  = (t & 3) * 16;

    const size_t sbase = (size_t)(b * 32 + qt) * 4;

    float m_s[4], l_s[4];
    float mstar = -1e30f;
#pragma unroll
    for (int s = 0; s < 4; ++s) {
        if (s < NS) {
            m_s[s] = g_pm[(sbase + s) * 64 + row];
            l_s[s] = g_pl[(sbase + s) * 64 + row];
            mstar = fmaxf(mstar, m_s[s]);
        }
    }
    float w[4], lsum = 0.f;
#pragma unroll
    for (int s = 0; s < 4; ++s) {
        if (s < NS) {
            w[s] = __expf(m_s[s] - mstar);
            lsum += w[s] * l_s[s];
        }
    }
    float inv = 1.f / lsum;

    float acc[16];
#pragma unroll
    for (int e = 0; e < 16; ++e) acc[e] = 0.f;
#pragma unroll
    for (int s = 0; s < 4; ++s) {
        if (s < NS) {
            const float* p = &g_pO[(sbase + s) * 4096 + row * 64 + cb];
#pragma unroll
            for (int u = 0; u < 4; ++u) {
                float4 v = *(const float4*)&p[u * 4];
                acc[u*4+0] += w[s] * v.x; acc[u*4+1] += w[s] * v.y;
                acc[u*4+2] += w[s] * v.z; acc[u*4+3] += w[s] * v.w;
            }
        }
    }
    float* o = &out[((size_t)b * Tn + qt * 64 + row) * Hn + cb];
#pragma unroll
    for (int u = 0; u < 4; ++u)
        *(float4*)&o[u * 4] = make_float4(acc[u*4+0] * inv, acc[u*4+1] * inv,
                                          acc[u*4+2] * inv, acc[u*4+3] * inv);
}

// ---------------------------------------------------------------------------
extern "C" void kernel_launch(void* const* d_in, const int* in_sizes, int n_in,
                              void* d_out, int out_size)
{
    (void)in_sizes; (void)n_in; (void)out_size;
    const float* x  = (const float*)d_in[0];
    const float* Wq = (const float*)d_in[1];
    const float* Wk = (const float*)d_in[2];
    const float* Wv = (const float*)d_in[3];
    float* out = (float*)d_out;

    qkv_mma<<<Mn / 32, 256>>>(x, Wq, Wk, Wv);
    attn_mma<<<dim3(80, 8), 128>>>(out);
    attn_merge<<<dim3(24, 8), 256>>>(out);
}